// round 13
// baseline (speedup 1.0000x reference)
#include <cuda_runtime.h>
#include <cuda_bf16.h>
#include <cuda_fp16.h>
#include <cstdint>
#include <cstddef>

// ============================================================================
// Problem constants
// ============================================================================
#define NROWS  65536
#define DDIM   128
#define KCB    2048
#define DHALF  64

#define TILE_M   128
#define CHUNK_N  128
#define NCHUNKS  (KCB / CHUNK_N)   // 16
#define NTILES   (NROWS / TILE_M)  // 512

#define KEYMASK  0xFFFFF800u       // clear 11 low mantissa bits (index field)

// ============================================================================
// Device scratch
// ============================================================================
__device__ __half g_Zh[(size_t)NROWS * DHALF];   // fp16 head of z_
__device__ __half g_Eh[KCB * DHALF];             // fp16 head of emb_
__device__ float  g_Zf[(size_t)NROWS * DHALF];   // exact fp32 z_
__device__ float  g_Ef[KCB * DHALF];             // exact fp32 emb_
__device__ float  g_c[KCB];                      // ||emb_k||^2
__device__ float  g_zz[NROWS];                   // ||z_n||^2

// ============================================================================
// PTX helpers (generic sm_80/sm_90 PTX only — no arch-'a' features)
// ============================================================================
__device__ __forceinline__ uint32_t smem_u32(const void* p) {
    uint32_t a;
    asm("{ .reg .u64 t; cvta.to.shared.u64 t, %1; cvt.u32.u64 %0, t; }"
        : "=r"(a) : "l"(p));
    return a;
}

__device__ __forceinline__ uint32_t sw128(uint32_t x) { return x ^ ((x >> 3) & 0x70); }

__device__ __forceinline__ void cp_async16(uint32_t dst, const void* src) {
    asm volatile("cp.async.cg.shared.global [%0], [%1], 16;" :: "r"(dst), "l"(src));
}
#define CP_COMMIT()  asm volatile("cp.async.commit_group;" ::: "memory")
#define CP_WAIT(n)   asm volatile("cp.async.wait_group %0;" :: "n"(n) : "memory")

// bulk async store smem -> global (async-proxy DMA path)
__device__ __forceinline__ void bulk_store(void* gdst, uint32_t ssrc, uint32_t bytes) {
    asm volatile("cp.async.bulk.global.shared::cta.bulk_group [%0], [%1], %2;"
                 :: "l"(gdst), "r"(ssrc), "r"(bytes) : "memory");
}
#define BULK_COMMIT() asm volatile("cp.async.bulk.commit_group;" ::: "memory")
#define BULK_WAIT0()  asm volatile("cp.async.bulk.wait_group 0;" ::: "memory")
#define FENCE_ASYNC_SHARED() asm volatile("fence.proxy.async.shared::cta;" ::: "memory")

__device__ __forceinline__ void ldsm_x4(uint32_t* r, uint32_t addr) {
    asm volatile("ldmatrix.sync.aligned.m8n8.x4.shared.b16 {%0,%1,%2,%3}, [%4];"
        : "=r"(r[0]), "=r"(r[1]), "=r"(r[2]), "=r"(r[3]) : "r"(addr));
}

__device__ __forceinline__ void mma_f16(float* c, const uint32_t* a,
                                        uint32_t b0, uint32_t b1) {
    asm volatile(
        "mma.sync.aligned.m16n8k16.row.col.f32.f16.f16.f32 "
        "{%0,%1,%2,%3}, {%4,%5,%6,%7}, {%8,%9}, {%0,%1,%2,%3};"
        : "+f"(c[0]), "+f"(c[1]), "+f"(c[2]), "+f"(c[3])
        : "r"(a[0]), "r"(a[1]), "r"(a[2]), "r"(a[3]), "r"(b0), "r"(b1));
}

// ============================================================================
// Prep kernel (merged): blocks [0,32) project emb, blocks [32,1056) project z.
// ============================================================================
#define PREP_PAD   132
#define PREP_SMEM  ((2 * 64 * PREP_PAD + 64) * 4)

__global__ void __launch_bounds__(256) prep_kernel(const float* __restrict__ z,
                                                   const float* __restrict__ emb,
                                                   const float* __restrict__ W,
                                                   const float* __restrict__ b) {
    extern __shared__ float sm[];
    float* Xs = sm;
    float* Ws = sm + 64 * PREP_PAD;
    float* bs = sm + 2 * 64 * PREP_PAD;
    const int tid = threadIdx.x;
    const int bx  = blockIdx.x;
    const int is_emb = (bx < 32);
    const float* X  = is_emb ? emb : z;
    const int row0  = (is_emb ? bx : (bx - 32)) * 64;

    for (int i = tid; i < 64 * 32; i += 256) {
        int r = i >> 5, d4 = i & 31;
        ((float4*)(Xs + r * PREP_PAD))[d4] = ((const float4*)(X + (size_t)(row0 + r) * DDIM))[d4];
        ((float4*)(Ws + r * PREP_PAD))[d4] = ((const float4*)(W + (size_t)r * DDIM))[d4];
    }
    if (tid < 64) bs[tid] = b[tid];
    __syncthreads();

    const int tx = tid & 15, ty = tid >> 4;
    const int r0 = ty * 4;
    float acc[4][4];
#pragma unroll
    for (int i = 0; i < 4; i++)
#pragma unroll
        for (int j = 0; j < 4; j++) acc[i][j] = bs[tx + 16 * j];

    const float4* Xs4 = (const float4*)Xs;
    const float4* Ws4 = (const float4*)Ws;
#pragma unroll 8
    for (int d4 = 0; d4 < 32; ++d4) {
        float4 a4[4], w4[4];
#pragma unroll
        for (int i = 0; i < 4; i++) a4[i] = Xs4[(r0 + i) * 33 + d4];
#pragma unroll
        for (int j = 0; j < 4; j++) w4[j] = Ws4[(tx + 16 * j) * 33 + d4];
#pragma unroll
        for (int i = 0; i < 4; i++)
#pragma unroll
            for (int j = 0; j < 4; j++) {
                acc[i][j] = fmaf(a4[i].x, w4[j].x, acc[i][j]);
                acc[i][j] = fmaf(a4[i].y, w4[j].y, acc[i][j]);
                acc[i][j] = fmaf(a4[i].z, w4[j].z, acc[i][j]);
                acc[i][j] = fmaf(a4[i].w, w4[j].w, acc[i][j]);
            }
    }

    __half* Oh = is_emb ? g_Eh : g_Zh;
    float*  Of = is_emb ? g_Ef : g_Zf;
    float* cOut = is_emb ? g_c : g_zz;

    float pn[4];
#pragma unroll
    for (int i = 0; i < 4; i++) {
        pn[i] = 0.0f;
#pragma unroll
        for (int j = 0; j < 4; j++) pn[i] = fmaf(acc[i][j], acc[i][j], pn[i]);
    }
#pragma unroll
    for (int off = 1; off < 16; off <<= 1)
#pragma unroll
        for (int i = 0; i < 4; i++)
            pn[i] += __shfl_xor_sync(0xffffffffu, pn[i], off);
    if (tx == 0)
#pragma unroll
        for (int i = 0; i < 4; i++) cOut[row0 + r0 + i] = pn[i];

#pragma unroll
    for (int i = 0; i < 4; i++)
#pragma unroll
        for (int j = 0; j < 4; j++) {
            float v = acc[i][j];
            size_t o = (size_t)(row0 + r0 + i) * DHALF + (tx + 16 * j);
            Oh[o] = __float2half_rn(v);
            Of[o] = v;
        }
}

// ============================================================================
// Main kernel — R12 skeleton; epilogue rewritten: hoisted cs (4x float2) and
// branchless packed-key (dist|idx) min1/min2 tracking.
//
// smem layout (bytes):
//   0:      args[128] i32      512
//   512:    zz_s[128] f32      512
//   1024:   wmax[8] f32        (pad to 1280)
//   1280:   red_k1[128][4] u32 2048 -> 3328
//   3328:   red_k2[128][4] u32 2048 -> 5376
//   5376:   (unused)           -> 7424
//   7424:   chunkmin[128][16]  8192 -> 15616  (int-keys)
//   15616:  cs[2048] f32       8192 -> 23808
//   23808:  zbuf[512] zeros    512  -> 24320 (pad to 24576)
//   24576:  A tile 16384       -> 40960
//   40960:  B bufs 2 x 16384   -> 73728
//   (refinement overlays zf[128][64] f32 = 32KB at A_OFF, after GEMM)
// ============================================================================
#define ARGS_OFF   0u
#define ZZS_OFF    512u
#define WMAX_OFF   1024u
#define RED_K1_OFF 1280u
#define RED_K2_OFF 3328u
#define CMIN_OFF   7424u
#define CS_OFF     15616u
#define ZBUF_OFF   23808u
#define A_OFF      24576u
#define B_OFF      40960u
#define MAIN_SMEM  73728

__device__ __forceinline__ void load_B_chunk(uint32_t sb, int chunk, int buf, int tid) {
    const char* src = (const char*)g_Eh + (size_t)chunk * CHUNK_N * 128;
    uint32_t dstbase = sb + B_OFF + (uint32_t)buf * 16384u;
    for (int i = tid; i < 1024; i += 256) {
        uint32_t off = (uint32_t)(i >> 3) * 128u + (uint32_t)(i & 7) * 16u;
        cp_async16(dstbase + sw128(off), src + off);
    }
}

__global__ void __launch_bounds__(256, 2)
vq_main_kernel(const float* __restrict__ emb,
               float* __restrict__ outQ, float* __restrict__ outOH) {
    extern __shared__ char smem[];
    const uint32_t sb = smem_u32(smem);
    const int tid  = threadIdx.x;
    const int lane = tid & 31;
    const int wid  = tid >> 5;
    const int wm   = wid >> 2;
    const int wn   = wid & 3;
    const int row0 = blockIdx.x * TILE_M;

    int*       args   = (int*)      (smem + ARGS_OFF);
    float*     zz_s   = (float*)    (smem + ZZS_OFF);
    float*     wmax_s = (float*)    (smem + WMAX_OFF);
    uint32_t*  red_k1 = (uint32_t*) (smem + RED_K1_OFF);
    uint32_t*  red_k2 = (uint32_t*) (smem + RED_K2_OFF);
    int*       cmin_s = (int*)      (smem + CMIN_OFF);
    float*     cs     = (float*)    (smem + CS_OFF);

    if (tid < 128) zz_s[tid] = g_zz[row0 + tid];
    for (int i = tid; i < 128 * 16; i += 256) cmin_s[i] = 0x7FFFFFFF;  // int max
    if (tid < 32)  // constant 512B zero buffer for bulk stores
        ((float4*)(smem + ZBUF_OFF))[tid] = make_float4(0.f, 0.f, 0.f, 0.f);

    float lmax = 0.0f;
    for (int i = tid; i < KCB; i += 256) {
        float v = g_c[i];
        cs[i] = v;
        lmax = fmaxf(lmax, v);
    }
#pragma unroll
    for (int off = 16; off >= 1; off >>= 1)
        lmax = fmaxf(lmax, __shfl_xor_sync(0xffffffffu, lmax, off));
    if (lane == 0) wmax_s[wid] = lmax;

    // A tile (fp16 head of z~), SW128 swizzled, resident
    {
        const char* src = (const char*)g_Zh + (size_t)row0 * 128;
        for (int i = tid; i < 1024; i += 256) {
            uint32_t off = (uint32_t)(i >> 3) * 128u + (uint32_t)(i & 7) * 16u;
            cp_async16(sb + A_OFF + sw128(off), src + off);
        }
    }
    load_B_chunk(sb, 0, 0, tid);
    CP_COMMIT();
    CP_WAIT(0);
    FENCE_ASYNC_SHARED();   // make zbuf visible to the async proxy
    __syncthreads();

    float cmax = wmax_s[0];
#pragma unroll
    for (int w = 1; w < 8; ++w) cmax = fmaxf(cmax, wmax_s[w]);

    // ldmatrix lane geometry
    const uint32_t r8     = (uint32_t)((lane & 7) + 8 * ((lane >> 3) & 1));
    const uint32_t xm     = (uint32_t)(lane & 7) * 16u;
    const uint32_t colSel = (uint32_t)((lane >> 4) & 1) * 16u;

    uint32_t aRow[4], bRow[2];
#pragma unroll
    for (int mt = 0; mt < 4; ++mt)
        aRow[mt] = (uint32_t)(wm * 64 + mt * 16) * 128u + r8 * 128u;
#pragma unroll
    for (int ng = 0; ng < 2; ++ng)
        bRow[ng] = (uint32_t)(wn * 32 + ng * 16) * 128u + r8 * 128u;

    int   rowIdx[4][2];
    float zzv[4][2];
#pragma unroll
    for (int mt = 0; mt < 4; ++mt)
#pragma unroll
        for (int h = 0; h < 2; ++h) {
            int row = wm * 64 + mt * 16 + (lane >> 2) + 8 * h;
            rowIdx[mt][h] = row;
            zzv[mt][h]    = zz_s[row];
        }

    float acc[4][4][4];
#pragma unroll
    for (int mt = 0; mt < 4; ++mt)
#pragma unroll
        for (int nt = 0; nt < 4; ++nt)
#pragma unroll
            for (int q = 0; q < 4; ++q) acc[mt][nt][q] = 0.0f;

    // persistent per-lane packed-key state: min1, min2 (index in low 11 bits)
    uint32_t k1[4][2], k2[4][2];
#pragma unroll
    for (int mt = 0; mt < 4; ++mt)
#pragma unroll
        for (int h = 0; h < 2; ++h) { k1[mt][h] = 0xFFFFFFFFu; k2[mt][h] = 0xFFFFFFFFu; }

    // ---- chunk loop ----
    for (int chunk = 0; chunk < NCHUNKS; ++chunk) {
        const int buf = chunk & 1;
        if (chunk + 1 < NCHUNKS) load_B_chunk(sb, chunk + 1, buf ^ 1, tid);
        CP_COMMIT();
        if (chunk + 1 < NCHUNKS) CP_WAIT(1); else CP_WAIT(0);
        __syncthreads();

        // ---- GEMM: hh product, 4 k-tiles ----
        const uint32_t aB = sb + A_OFF;
        const uint32_t bB = sb + B_OFF + (uint32_t)buf * 16384u;
#pragma unroll
        for (int kt = 0; kt < 4; ++kt) {
            const uint32_t kc = ((uint32_t)(kt * 32) + colSel) ^ xm;
            uint32_t afr[4][4];
#pragma unroll
            for (int mt = 0; mt < 4; ++mt) ldsm_x4(afr[mt], aB + aRow[mt] + kc);
            uint32_t bfr[2][4];
#pragma unroll
            for (int ng = 0; ng < 2; ++ng) ldsm_x4(bfr[ng], bB + bRow[ng] + kc);
#pragma unroll
            for (int mt = 0; mt < 4; ++mt)
#pragma unroll
                for (int nt = 0; nt < 4; ++nt)
                    mma_f16(acc[mt][nt], afr[mt],
                            bfr[nt >> 1][nt & 1], bfr[nt >> 1][(nt & 1) + 2]);
        }

        // ---- epilogue: hoisted cs, packed keys, branchless min1/min2 ----
        const int colbase = chunk * CHUNK_N + wn * 32 + 2 * (lane & 3);
        float2 csv[4];
#pragma unroll
        for (int nt = 0; nt < 4; ++nt)
            csv[nt] = *(const float2*)(cs + colbase + nt * 8);

#pragma unroll
        for (int mt = 0; mt < 4; ++mt)
#pragma unroll
            for (int h = 0; h < 2; ++h) {
                const float zz = zzv[mt][h];
                uint32_t cminloc = 0xFFFFFFFFu;
#pragma unroll
                for (int nt = 0; nt < 4; ++nt) {
                    const uint32_t c0 = (uint32_t)(colbase + nt * 8);
                    float d0 = fmaf(-2.0f, acc[mt][nt][2 * h + 0], zz + csv[nt].x);
                    float d1 = fmaf(-2.0f, acc[mt][nt][2 * h + 1], zz + csv[nt].y);
                    uint32_t key0 = (__float_as_uint(d0) & KEYMASK) | c0;
                    uint32_t key1 = (__float_as_uint(d1) & KEYMASK) | (c0 + 1u);
                    k2[mt][h] = min(k2[mt][h], max(k1[mt][h], key0));
                    k1[mt][h] = min(k1[mt][h], key0);
                    k2[mt][h] = min(k2[mt][h], max(k1[mt][h], key1));
                    k1[mt][h] = min(k1[mt][h], key1);
                    cminloc = min(cminloc, min(key0, key1));
                    acc[mt][nt][2 * h + 0] = 0.0f;
                    acc[mt][nt][2 * h + 1] = 0.0f;
                }
                cminloc = min(cminloc, __shfl_xor_sync(0xffffffffu, cminloc, 1));
                cminloc = min(cminloc, __shfl_xor_sync(0xffffffffu, cminloc, 2));
                if ((lane & 3) == 0)
                    atomicMin(&cmin_s[rowIdx[mt][h] * 16 + chunk], (int)cminloc);
            }

        // ---- one-hot zero-fill via async-proxy bulk stores (fire & forget) ----
        if (tid < 128) {
            float* gdst = outOH + (size_t)(row0 + tid) * KCB + chunk * CHUNK_N;
            bulk_store(gdst, sb + ZBUF_OFF, 512u);
            BULK_COMMIT();
        }

        __syncthreads();
    }

    // ---- quad merge of (k1,k2), then cross-warp ----
#pragma unroll
    for (int mt = 0; mt < 4; ++mt)
#pragma unroll
        for (int h = 0; h < 2; ++h) {
            uint32_t vk1 = k1[mt][h], vk2 = k2[mt][h];
#pragma unroll
            for (int off = 1; off < 4; off <<= 1) {
                uint32_t o1 = __shfl_xor_sync(0xffffffffu, vk1, off);
                uint32_t o2 = __shfl_xor_sync(0xffffffffu, vk2, off);
                uint32_t n2 = min(max(vk1, o1), min(vk2, o2));
                vk1 = min(vk1, o1);
                vk2 = n2;
            }
            if ((lane & 3) == 0) {
                int row = rowIdx[mt][h];
                red_k1[row * 4 + wn] = vk1;
                red_k2[row * 4 + wn] = vk2;
            }
        }
    __syncthreads();

    if (tid < 128) {
        uint32_t vk1 = red_k1[tid * 4], vk2 = red_k2[tid * 4];
#pragma unroll
        for (int w = 1; w < 4; ++w) {
            uint32_t o1 = red_k1[tid * 4 + w];
            uint32_t o2 = red_k2[tid * 4 + w];
            uint32_t n2 = min(max(vk1, o1), min(vk2, o2));
            vk1 = min(vk1, o1);
            vk2 = n2;
        }
        args[tid] = (int)(vk1 & 0x7FFu);
        red_k1[tid * 4] = vk1;   // final min key
        red_k2[tid * 4] = vk2;   // final second key
    }
    __syncthreads();

    // ---- load exact z_ tile into smem overlay (GEMM buffers dead now) ----
    float* zf = (float*)(smem + A_OFF);
    for (int i = tid; i < 128 * 16; i += 256)
        ((float4*)zf)[i] = ((const float4*)(g_Zf + (size_t)row0 * DHALF))[i];
    __syncthreads();

    // ---- refinement: only ambiguous rows; only surviving chunks; exact fp32 ----
    for (int rr = 0; rr < 16; ++rr) {
        const int row = wid * 16 + rr;
        const float fb1 = __uint_as_float(red_k1[row * 4] & KEYMASK);
        const float fb2 = __uint_as_float(red_k2[row * 4] & KEYMASK);
        const float zz  = zz_s[row];
        // margin: 2x one-sided hh error + 2x key truncation + slack
        const float M = 0.0052f * sqrtf(zz * cmax) + 0.001f * (zz + cmax) + 0.02f;
        if (fb2 - fb1 >= M) continue;          // key argmin provably exact

        const float thr = fb1 + M;
        const float4* zrow4 = (const float4*)(zf + row * DHALF);
        float bd = __int_as_float(0x7f800000);
        int   bi = KCB;
        for (int ch = 0; ch < NCHUNKS; ++ch) {
            if (__uint_as_float((uint32_t)cmin_s[row * 16 + ch] & KEYMASK) > thr) continue;
            const int k0 = ch * CHUNK_N + lane * 4;
#pragma unroll
            for (int j = 0; j < 4; ++j) {
                const int k = k0 + j;
                const float4* e4 = (const float4*)(g_Ef + (size_t)k * DHALF);
                float s = 0.0f;
#pragma unroll
                for (int d4 = 0; d4 < 16; ++d4) {
                    float4 zv = zrow4[d4];
                    float4 ev = __ldg(e4 + d4);
                    s = fmaf(zv.x, ev.x, s);
                    s = fmaf(zv.y, ev.y, s);
                    s = fmaf(zv.z, ev.z, s);
                    s = fmaf(zv.w, ev.w, s);
                }
                float d = zz + cs[k] - 2.0f * s;
                if (d < bd || (d == bd && k < bi)) { bd = d; bi = k; }
            }
        }
#pragma unroll
        for (int off = 16; off >= 1; off >>= 1) {
            float od = __shfl_xor_sync(0xffffffffu, bd, off);
            int   oi = __shfl_xor_sync(0xffffffffu, bi, off);
            if (od < bd || (od == bd && oi < bi)) { bd = od; bi = oi; }
        }
        if (lane == 0) args[row] = bi;
    }
    __syncthreads();

    // ---- wait for ALL async zero stores, then scatter the 1.0s ----
    BULK_WAIT0();
    __syncthreads();
    if (tid < 128)
        outOH[(size_t)(row0 + tid) * KCB + args[tid]] = 1.0f;

    // ---- quantized gather ----
    {
        const float4* e4 = (const float4*)emb;
        for (int i = tid; i < 128 * 32; i += 256) {
            int r = i >> 5, c = i & 31;
            float4 v = __ldg(e4 + (size_t)args[r] * 32 + c);
            __stcs((float4*)outQ + (size_t)(row0 + r) * 32 + c, v);
        }
    }
}

// ============================================================================
// Launch
// ============================================================================
extern "C" void kernel_launch(void* const* d_in, const int* in_sizes, int n_in,
                              void* d_out, int out_size) {
    const float* z   = (const float*)d_in[0];
    const float* W   = (const float*)d_in[1];
    const float* b   = (const float*)d_in[2];
    const float* emb = (const float*)d_in[3];

    float* outQ  = (float*)d_out;                 // [N, 128]
    float* outOH = outQ + (size_t)NROWS * DDIM;   // [N, 2048]

    cudaFuncSetAttribute(prep_kernel, cudaFuncAttributeMaxDynamicSharedMemorySize, PREP_SMEM);
    cudaFuncSetAttribute(vq_main_kernel, cudaFuncAttributeMaxDynamicSharedMemorySize, MAIN_SMEM);

    prep_kernel<<<32 + NROWS / 64, 256, PREP_SMEM>>>(z, emb, W, b);
    vq_main_kernel<<<NTILES, 256, MAIN_SMEM>>>(emb, outQ, outOH);
}

// round 14
// speedup vs baseline: 1.1633x; 1.1633x over previous
#include <cuda_runtime.h>
#include <cuda_bf16.h>
#include <cuda_fp16.h>
#include <cstdint>
#include <cstddef>

// ============================================================================
// Problem constants
// ============================================================================
#define NROWS  65536
#define DDIM   128
#define KCB    2048
#define DHALF  64

#define TILE_M   128
#define CHUNK_N  128
#define NCHUNKS  (KCB / CHUNK_N)   // 16
#define NTILES   (NROWS / TILE_M)  // 512

#define CBIAS    1024.0f           // positivity bias folded into smem cs copy

// ============================================================================
// Device scratch
// ============================================================================
__device__ __half g_Zh[(size_t)NROWS * DHALF];   // fp16 head of z_
__device__ __half g_Eh[KCB * DHALF];             // fp16 head of emb_
__device__ float  g_Zf[(size_t)NROWS * DHALF];   // exact fp32 z_
__device__ float  g_Ef[KCB * DHALF];             // exact fp32 emb_
__device__ float  g_c[KCB];                      // ||emb_k||^2 (exact)
__device__ float  g_zz[NROWS];                   // ||z_n||^2

// ============================================================================
// PTX helpers (generic sm_80/sm_90 PTX only — no arch-'a' features)
// ============================================================================
__device__ __forceinline__ uint32_t smem_u32(const void* p) {
    uint32_t a;
    asm("{ .reg .u64 t; cvta.to.shared.u64 t, %1; cvt.u32.u64 %0, t; }"
        : "=r"(a) : "l"(p));
    return a;
}

__device__ __forceinline__ uint32_t sw128(uint32_t x) { return x ^ ((x >> 3) & 0x70); }

__device__ __forceinline__ void cp_async16(uint32_t dst, const void* src) {
    asm volatile("cp.async.cg.shared.global [%0], [%1], 16;" :: "r"(dst), "l"(src));
}
#define CP_COMMIT()  asm volatile("cp.async.commit_group;" ::: "memory")
#define CP_WAIT(n)   asm volatile("cp.async.wait_group %0;" :: "n"(n) : "memory")

// bulk async store smem -> global (async-proxy DMA path)
__device__ __forceinline__ void bulk_store(void* gdst, uint32_t ssrc, uint32_t bytes) {
    asm volatile("cp.async.bulk.global.shared::cta.bulk_group [%0], [%1], %2;"
                 :: "l"(gdst), "r"(ssrc), "r"(bytes) : "memory");
}
#define BULK_COMMIT() asm volatile("cp.async.bulk.commit_group;" ::: "memory")
#define BULK_WAIT0()  asm volatile("cp.async.bulk.wait_group 0;" ::: "memory")
#define FENCE_ASYNC_SHARED() asm volatile("fence.proxy.async.shared::cta;" ::: "memory")

__device__ __forceinline__ void ldsm_x4(uint32_t* r, uint32_t addr) {
    asm volatile("ldmatrix.sync.aligned.m8n8.x4.shared.b16 {%0,%1,%2,%3}, [%4];"
        : "=r"(r[0]), "=r"(r[1]), "=r"(r[2]), "=r"(r[3]) : "r"(addr));
}

__device__ __forceinline__ void mma_f16(float* c, const uint32_t* a,
                                        uint32_t b0, uint32_t b1) {
    asm volatile(
        "mma.sync.aligned.m16n8k16.row.col.f32.f16.f16.f32 "
        "{%0,%1,%2,%3}, {%4,%5,%6,%7}, {%8,%9}, {%0,%1,%2,%3};"
        : "+f"(c[0]), "+f"(c[1]), "+f"(c[2]), "+f"(c[3])
        : "r"(a[0]), "r"(a[1]), "r"(a[2]), "r"(a[3]), "r"(b0), "r"(b1));
}

// ============================================================================
// Prep kernel (merged): blocks [0,32) project emb, blocks [32,1056) project z.
// ============================================================================
#define PREP_PAD   132
#define PREP_SMEM  ((2 * 64 * PREP_PAD + 64) * 4)

__global__ void __launch_bounds__(256) prep_kernel(const float* __restrict__ z,
                                                   const float* __restrict__ emb,
                                                   const float* __restrict__ W,
                                                   const float* __restrict__ b) {
    extern __shared__ float sm[];
    float* Xs = sm;
    float* Ws = sm + 64 * PREP_PAD;
    float* bs = sm + 2 * 64 * PREP_PAD;
    const int tid = threadIdx.x;
    const int bx  = blockIdx.x;
    const int is_emb = (bx < 32);
    const float* X  = is_emb ? emb : z;
    const int row0  = (is_emb ? bx : (bx - 32)) * 64;

    for (int i = tid; i < 64 * 32; i += 256) {
        int r = i >> 5, d4 = i & 31;
        ((float4*)(Xs + r * PREP_PAD))[d4] = ((const float4*)(X + (size_t)(row0 + r) * DDIM))[d4];
        ((float4*)(Ws + r * PREP_PAD))[d4] = ((const float4*)(W + (size_t)r * DDIM))[d4];
    }
    if (tid < 64) bs[tid] = b[tid];
    __syncthreads();

    const int tx = tid & 15, ty = tid >> 4;
    const int r0 = ty * 4;
    float acc[4][4];
#pragma unroll
    for (int i = 0; i < 4; i++)
#pragma unroll
        for (int j = 0; j < 4; j++) acc[i][j] = bs[tx + 16 * j];

    const float4* Xs4 = (const float4*)Xs;
    const float4* Ws4 = (const float4*)Ws;
#pragma unroll 8
    for (int d4 = 0; d4 < 32; ++d4) {
        float4 a4[4], w4[4];
#pragma unroll
        for (int i = 0; i < 4; i++) a4[i] = Xs4[(r0 + i) * 33 + d4];
#pragma unroll
        for (int j = 0; j < 4; j++) w4[j] = Ws4[(tx + 16 * j) * 33 + d4];
#pragma unroll
        for (int i = 0; i < 4; i++)
#pragma unroll
            for (int j = 0; j < 4; j++) {
                acc[i][j] = fmaf(a4[i].x, w4[j].x, acc[i][j]);
                acc[i][j] = fmaf(a4[i].y, w4[j].y, acc[i][j]);
                acc[i][j] = fmaf(a4[i].z, w4[j].z, acc[i][j]);
                acc[i][j] = fmaf(a4[i].w, w4[j].w, acc[i][j]);
            }
    }

    __half* Oh = is_emb ? g_Eh : g_Zh;
    float*  Of = is_emb ? g_Ef : g_Zf;
    float* cOut = is_emb ? g_c : g_zz;

    float pn[4];
#pragma unroll
    for (int i = 0; i < 4; i++) {
        pn[i] = 0.0f;
#pragma unroll
        for (int j = 0; j < 4; j++) pn[i] = fmaf(acc[i][j], acc[i][j], pn[i]);
    }
#pragma unroll
    for (int off = 1; off < 16; off <<= 1)
#pragma unroll
        for (int i = 0; i < 4; i++)
            pn[i] += __shfl_xor_sync(0xffffffffu, pn[i], off);
    if (tx == 0)
#pragma unroll
        for (int i = 0; i < 4; i++) cOut[row0 + r0 + i] = pn[i];

#pragma unroll
    for (int i = 0; i < 4; i++)
#pragma unroll
        for (int j = 0; j < 4; j++) {
            float v = acc[i][j];
            size_t o = (size_t)(row0 + r0 + i) * DHALF + (tx + 16 * j);
            Oh[o] = __float2half_rn(v);
            Of[o] = v;
        }
}

// ============================================================================
// Main kernel — R12 skeleton; epilogue = R7 predicated best/second logic but
// in zz-free biased-c space: rank key d' = (c_k + 1024) - 2*s.
//
// smem layout (bytes):
//   0:      args[128] i32      512
//   512:    zz_s[128] f32      512
//   1024:   wmax[8] f32        (pad to 1280)
//   1280:   red_d [128][4]     2048 -> 3328
//   3328:   red_i [128][4]     2048 -> 5376
//   5376:   red_d2[128][4]     2048 -> 7424
//   7424:   chunkmin[128][16]  8192 -> 15616   (biased-float bits)
//   15616:  cs[2048] f32       8192 -> 23808   (c + 1024)
//   23808:  zbuf[512] zeros    512  -> 24320 (pad to 24576)
//   24576:  A tile 16384       -> 40960
//   40960:  B bufs 2 x 16384   -> 73728
//   (refinement overlays zf[128][64] f32 = 32KB at A_OFF, after GEMM)
// ============================================================================
#define ARGS_OFF   0u
#define ZZS_OFF    512u
#define WMAX_OFF   1024u
#define RED_D_OFF  1280u
#define RED_I_OFF  3328u
#define RED_D2_OFF 5376u
#define CMIN_OFF   7424u
#define CS_OFF     15616u
#define ZBUF_OFF   23808u
#define A_OFF      24576u
#define B_OFF      40960u
#define MAIN_SMEM  73728

__device__ __forceinline__ void load_B_chunk(uint32_t sb, int chunk, int buf, int tid) {
    const char* src = (const char*)g_Eh + (size_t)chunk * CHUNK_N * 128;
    uint32_t dstbase = sb + B_OFF + (uint32_t)buf * 16384u;
    for (int i = tid; i < 1024; i += 256) {
        uint32_t off = (uint32_t)(i >> 3) * 128u + (uint32_t)(i & 7) * 16u;
        cp_async16(dstbase + sw128(off), src + off);
    }
}

__global__ void __launch_bounds__(256, 2)
vq_main_kernel(const float* __restrict__ emb,
               float* __restrict__ outQ, float* __restrict__ outOH) {
    extern __shared__ char smem[];
    const uint32_t sb = smem_u32(smem);
    const int tid  = threadIdx.x;
    const int lane = tid & 31;
    const int wid  = tid >> 5;
    const int wm   = wid >> 2;
    const int wn   = wid & 3;
    const int row0 = blockIdx.x * TILE_M;

    int*   args   = (int*)  (smem + ARGS_OFF);
    float* zz_s   = (float*)(smem + ZZS_OFF);
    float* wmax_s = (float*)(smem + WMAX_OFF);
    float* red_d  = (float*)(smem + RED_D_OFF);
    int*   red_i  = (int*)  (smem + RED_I_OFF);
    float* red_d2 = (float*)(smem + RED_D2_OFF);
    int*   cmin_s = (int*)  (smem + CMIN_OFF);
    float* cs     = (float*)(smem + CS_OFF);

    if (tid < 128) zz_s[tid] = g_zz[row0 + tid];
    for (int i = tid; i < 128 * 16; i += 256) cmin_s[i] = 0x7f800000;  // +inf bits
    if (tid < 32)  // constant 512B zero buffer for bulk stores
        ((float4*)(smem + ZBUF_OFF))[tid] = make_float4(0.f, 0.f, 0.f, 0.f);

    float lmax = 0.0f;
    for (int i = tid; i < KCB; i += 256) {
        float v = g_c[i];
        cs[i] = v + CBIAS;           // biased copy for the scan
        lmax = fmaxf(lmax, v);       // raw max for the margin
    }
#pragma unroll
    for (int off = 16; off >= 1; off >>= 1)
        lmax = fmaxf(lmax, __shfl_xor_sync(0xffffffffu, lmax, off));
    if (lane == 0) wmax_s[wid] = lmax;

    // A tile (fp16 head of z~), SW128 swizzled, resident
    {
        const char* src = (const char*)g_Zh + (size_t)row0 * 128;
        for (int i = tid; i < 1024; i += 256) {
            uint32_t off = (uint32_t)(i >> 3) * 128u + (uint32_t)(i & 7) * 16u;
            cp_async16(sb + A_OFF + sw128(off), src + off);
        }
    }
    load_B_chunk(sb, 0, 0, tid);
    CP_COMMIT();
    CP_WAIT(0);
    FENCE_ASYNC_SHARED();   // make zbuf visible to the async proxy
    __syncthreads();

    float cmax = wmax_s[0];
#pragma unroll
    for (int w = 1; w < 8; ++w) cmax = fmaxf(cmax, wmax_s[w]);

    // ldmatrix lane geometry
    const uint32_t r8     = (uint32_t)((lane & 7) + 8 * ((lane >> 3) & 1));
    const uint32_t xm     = (uint32_t)(lane & 7) * 16u;
    const uint32_t colSel = (uint32_t)((lane >> 4) & 1) * 16u;

    uint32_t aRow[4], bRow[2];
#pragma unroll
    for (int mt = 0; mt < 4; ++mt)
        aRow[mt] = (uint32_t)(wm * 64 + mt * 16) * 128u + r8 * 128u;
#pragma unroll
    for (int ng = 0; ng < 2; ++ng)
        bRow[ng] = (uint32_t)(wn * 32 + ng * 16) * 128u + r8 * 128u;

    int rowIdx[4][2];
#pragma unroll
    for (int mt = 0; mt < 4; ++mt)
#pragma unroll
        for (int h = 0; h < 2; ++h)
            rowIdx[mt][h] = wm * 64 + mt * 16 + (lane >> 2) + 8 * h;

    float acc[4][4][4];
#pragma unroll
    for (int mt = 0; mt < 4; ++mt)
#pragma unroll
        for (int nt = 0; nt < 4; ++nt)
#pragma unroll
            for (int q = 0; q < 4; ++q) acc[mt][nt][q] = 0.0f;

    // persistent per-lane running state (biased-c space, zz-free)
    float b1[4][2], b2[4][2];
    int   i1[4][2];
#pragma unroll
    for (int mt = 0; mt < 4; ++mt)
#pragma unroll
        for (int h = 0; h < 2; ++h) {
            b1[mt][h] = __int_as_float(0x7f800000);
            b2[mt][h] = __int_as_float(0x7f800000);
            i1[mt][h] = 0;
        }

    // ---- chunk loop ----
    for (int chunk = 0; chunk < NCHUNKS; ++chunk) {
        const int buf = chunk & 1;
        if (chunk + 1 < NCHUNKS) load_B_chunk(sb, chunk + 1, buf ^ 1, tid);
        CP_COMMIT();
        if (chunk + 1 < NCHUNKS) CP_WAIT(1); else CP_WAIT(0);
        __syncthreads();

        // ---- GEMM: hh product, 4 k-tiles ----
        const uint32_t aB = sb + A_OFF;
        const uint32_t bB = sb + B_OFF + (uint32_t)buf * 16384u;
#pragma unroll
        for (int kt = 0; kt < 4; ++kt) {
            const uint32_t kc = ((uint32_t)(kt * 32) + colSel) ^ xm;
            uint32_t afr[4][4];
#pragma unroll
            for (int mt = 0; mt < 4; ++mt) ldsm_x4(afr[mt], aB + aRow[mt] + kc);
            uint32_t bfr[2][4];
#pragma unroll
            for (int ng = 0; ng < 2; ++ng) ldsm_x4(bfr[ng], bB + bRow[ng] + kc);
#pragma unroll
            for (int mt = 0; mt < 4; ++mt)
#pragma unroll
                for (int nt = 0; nt < 4; ++nt)
                    mma_f16(acc[mt][nt], afr[mt],
                            bfr[nt >> 1][nt & 1], bfr[nt >> 1][(nt & 1) + 2]);
        }

        // ---- epilogue: zz-free biased keys, hoisted cs, predicated updates ----
        const int colbase = chunk * CHUNK_N + wn * 32 + 2 * (lane & 3);
        float2 csv[4];
#pragma unroll
        for (int nt = 0; nt < 4; ++nt)
            csv[nt] = *(const float2*)(cs + colbase + nt * 8);

#pragma unroll
        for (int mt = 0; mt < 4; ++mt)
#pragma unroll
            for (int h = 0; h < 2; ++h) {
                float cmin = __int_as_float(0x7f800000);
#pragma unroll
                for (int nt = 0; nt < 4; ++nt) {
                    const int c0 = colbase + nt * 8;
                    float d0 = fmaf(-2.0f, acc[mt][nt][2 * h + 0], csv[nt].x);
                    float d1 = fmaf(-2.0f, acc[mt][nt][2 * h + 1], csv[nt].y);
                    if (d0 < b1[mt][h]) { b2[mt][h] = b1[mt][h]; b1[mt][h] = d0; i1[mt][h] = c0; }
                    else                 b2[mt][h] = fminf(b2[mt][h], d0);
                    if (d1 < b1[mt][h]) { b2[mt][h] = b1[mt][h]; b1[mt][h] = d1; i1[mt][h] = c0 + 1; }
                    else                 b2[mt][h] = fminf(b2[mt][h], d1);
                    cmin = fminf(cmin, fminf(d0, d1));
                    acc[mt][nt][2 * h + 0] = 0.0f;
                    acc[mt][nt][2 * h + 1] = 0.0f;
                }
                cmin = fminf(cmin, __shfl_xor_sync(0xffffffffu, cmin, 1));
                cmin = fminf(cmin, __shfl_xor_sync(0xffffffffu, cmin, 2));
                if ((lane & 3) == 0)
                    atomicMin(&cmin_s[rowIdx[mt][h] * 16 + chunk], __float_as_int(cmin));
            }

        // ---- one-hot zero-fill via async-proxy bulk stores (fire & forget) ----
        if (tid < 128) {
            float* gdst = outOH + (size_t)(row0 + tid) * KCB + chunk * CHUNK_N;
            bulk_store(gdst, sb + ZBUF_OFF, 512u);
            BULK_COMMIT();
        }

        __syncthreads();
    }

    // ---- quad merge of (b1,i1,b2), then cross-warp ----
#pragma unroll
    for (int mt = 0; mt < 4; ++mt)
#pragma unroll
        for (int h = 0; h < 2; ++h) {
            float vb1 = b1[mt][h], vb2 = b2[mt][h];
            int   vi1 = i1[mt][h];
#pragma unroll
            for (int off = 1; off < 4; off <<= 1) {
                float ob1 = __shfl_xor_sync(0xffffffffu, vb1, off);
                int   oi1 = __shfl_xor_sync(0xffffffffu, vi1, off);
                float ob2 = __shfl_xor_sync(0xffffffffu, vb2, off);
                bool take = (ob1 < vb1) || (ob1 == vb1 && oi1 < vi1);
                float nb2 = take ? fminf(vb1, ob2) : fminf(vb2, ob1);
                if (take) { vb1 = ob1; vi1 = oi1; }
                vb2 = nb2;
            }
            if ((lane & 3) == 0) {
                int row = rowIdx[mt][h];
                red_d [row * 4 + wn] = vb1;
                red_i [row * 4 + wn] = vi1;
                red_d2[row * 4 + wn] = vb2;
            }
        }
    __syncthreads();

    if (tid < 128) {
        float vb1 = red_d[tid * 4], vb2 = red_d2[tid * 4];
        int   vi1 = red_i[tid * 4];
#pragma unroll
        for (int w = 1; w < 4; ++w) {
            float ob1 = red_d[tid * 4 + w];
            int   oi1 = red_i[tid * 4 + w];
            float ob2 = red_d2[tid * 4 + w];
            bool take = (ob1 < vb1) || (ob1 == vb1 && oi1 < vi1);
            float nb2 = take ? fminf(vb1, ob2) : fminf(vb2, ob1);
            if (take) { vb1 = ob1; vi1 = oi1; }
            vb2 = nb2;
        }
        args[tid] = vi1;
        red_d [tid * 4] = vb1;   // final best   (biased space)
        red_d2[tid * 4] = vb2;   // final second (biased space)
    }
    __syncthreads();

    // ---- load exact z_ tile into smem overlay (GEMM buffers dead now) ----
    float* zf = (float*)(smem + A_OFF);
    for (int i = tid; i < 128 * 16; i += 256)
        ((float4*)zf)[i] = ((const float4*)(g_Zf + (size_t)row0 * DHALF))[i];
    __syncthreads();

    // ---- refinement: only ambiguous rows; only surviving chunks; exact fp32 ----
    for (int rr = 0; rr < 16; ++rr) {
        const int row = wid * 16 + rr;
        const float fb1 = red_d[row * 4];
        const float fb2 = red_d2[row * 4];
        const float zz  = zz_s[row];
        // hh error bound (both sides) + bias rounding + slack; bias cancels in diff
        const float M = 0.0052f * sqrtf(zz * cmax) + 0.02f;
        if (fb2 - fb1 >= M) continue;          // scan argmin provably exact

        const float thr = fb1 + M;             // biased space, matches cmin_s
        const float4* zrow4 = (const float4*)(zf + row * DHALF);
        float bd = __int_as_float(0x7f800000);
        int   bi = KCB;
        for (int ch = 0; ch < NCHUNKS; ++ch) {
            if (__int_as_float(cmin_s[row * 16 + ch]) > thr) continue;
            const int k0 = ch * CHUNK_N + lane * 4;
#pragma unroll
            for (int j = 0; j < 4; ++j) {
                const int k = k0 + j;
                const float4* e4 = (const float4*)(g_Ef + (size_t)k * DHALF);
                float s = 0.0f;
#pragma unroll
                for (int d4 = 0; d4 < 16; ++d4) {
                    float4 zv = zrow4[d4];
                    float4 ev = __ldg(e4 + d4);
                    s = fmaf(zv.x, ev.x, s);
                    s = fmaf(zv.y, ev.y, s);
                    s = fmaf(zv.z, ev.z, s);
                    s = fmaf(zv.w, ev.w, s);
                }
                // exact fp32 distance: true c from g_c (cs is biased/rounded)
                float d = zz + __ldg(g_c + k) - 2.0f * s;
                if (d < bd || (d == bd && k < bi)) { bd = d; bi = k; }
            }
        }
#pragma unroll
        for (int off = 16; off >= 1; off >>= 1) {
            float od = __shfl_xor_sync(0xffffffffu, bd, off);
            int   oi = __shfl_xor_sync(0xffffffffu, bi, off);
            if (od < bd || (od == bd && oi < bi)) { bd = od; bi = oi; }
        }
        if (lane == 0) args[row] = bi;
    }
    __syncthreads();

    // ---- wait for ALL async zero stores, then scatter the 1.0s ----
    BULK_WAIT0();
    __syncthreads();
    if (tid < 128)
        outOH[(size_t)(row0 + tid) * KCB + args[tid]] = 1.0f;

    // ---- quantized gather ----
    {
        const float4* e4 = (const float4*)emb;
        for (int i = tid; i < 128 * 32; i += 256) {
            int r = i >> 5, c = i & 31;
            float4 v = __ldg(e4 + (size_t)args[r] * 32 + c);
            __stcs((float4*)outQ + (size_t)(row0 + r) * 32 + c, v);
        }
    }
}

// ============================================================================
// Launch
// ============================================================================
extern "C" void kernel_launch(void* const* d_in, const int* in_sizes, int n_in,
                              void* d_out, int out_size) {
    const float* z   = (const float*)d_in[0];
    const float* W   = (const float*)d_in[1];
    const float* b   = (const float*)d_in[2];
    const float* emb = (const float*)d_in[3];

    float* outQ  = (float*)d_out;                 // [N, 128]
    float* outOH = outQ + (size_t)NROWS * DDIM;   // [N, 2048]

    cudaFuncSetAttribute(prep_kernel, cudaFuncAttributeMaxDynamicSharedMemorySize, PREP_SMEM);
    cudaFuncSetAttribute(vq_main_kernel, cudaFuncAttributeMaxDynamicSharedMemorySize, MAIN_SMEM);

    prep_kernel<<<32 + NROWS / 64, 256, PREP_SMEM>>>(z, emb, W, b);
    vq_main_kernel<<<NTILES, 256, MAIN_SMEM>>>(emb, outQ, outOH);
}